// round 15
// baseline (speedup 1.0000x reference)
#include <cuda_runtime.h>
#include <cuda_fp16.h>
#include <cstdint>

#define C_    256
#define P_    65536
#define NC_   1024
#define NCHW_ 16777216

// ---- device scratch -------------------------------------------------------
__device__ __half g_ch[NC_ * C_];          // codebook fp16, K-major
__device__ float g_cbT[C_ * NC_];          // codebook transposed [k][n] f32
__device__ float g_ee[NC_];
__device__ int   g_idx[P_];
__device__ int   g_nA, g_nB;
__device__ int4  g_flA[P_];                // (pixel, cand0, cand1, cand2)
__device__ int   g_flB[P_];

// ---- k_main smem layout (BM=128, BN=32, double-buffered B) ----------------
#define AW       132                    // words per row (132%32==4 -> conflict-free)
#define SBB      16896                  // one B buffer: 32 * 132 * 4
#define OFF_B    67584                  // SA: 128 x 132 words
#define OFF_EEH  101376                 // 1024 f32
#define OFF_U3   105472                 // float[2][128][3]
#define OFF_I3   108544                 // int[2][128][3]
#define SMEM_DYN 111616                 // ~109KB -> 2 CTAs/SM
// post-loop aliases: tile = smem[0..33792), s_idx = smem+OFF_B (512B)

#define TIE_T    6.5e-5f                // 3.1e-5 ref-jitter bound + 6.5 sigma

// ---------------------------------------------------------------------------
// codebook -> fp16 + transpose + exact ||e||^2 ; resets flag counters
__global__ void k_cbsplit(const float* __restrict__ cb) {
    if (blockIdx.x == 0 && threadIdx.x == 0) { g_nA = 0; g_nB = 0; }
    int gw   = (blockIdx.x * blockDim.x + threadIdx.x) >> 5;
    int lane = threadIdx.x & 31;
    if (gw >= NC_) return;
    const float* r = cb + (size_t)gw * C_;
    float acc = 0.f;
    #pragma unroll
    for (int k = lane; k < C_; k += 32) {
        float v = r[k];
        acc = fmaf(v, v, acc);
        g_ch[(size_t)gw * C_ + k] = __float2half_rn(v);
        g_cbT[(size_t)k * NC_ + gw] = v;
    }
    #pragma unroll
    for (int o = 16; o; o >>= 1) acc += __shfl_xor_sync(0xffffffffu, acc, o);
    if (!lane) g_ee[gw] = acc;
}

// ---------------------------------------------------------------------------
__device__ __forceinline__ void mma_f16(float* c, uint32_t a0, uint32_t a1,
                                        uint32_t a2, uint32_t a3,
                                        uint32_t b0, uint32_t b1) {
    asm volatile(
        "mma.sync.aligned.m16n8k16.row.col.f32.f16.f16.f32 "
        "{%0,%1,%2,%3}, {%4,%5,%6,%7}, {%8,%9}, {%0,%1,%2,%3};"
        : "+f"(c[0]), "+f"(c[1]), "+f"(c[2]), "+f"(c[3])
        : "r"(a0), "r"(a1), "r"(a2), "r"(a3), "r"(b0), "r"(b1));
}

// stable 3-slot sorted insert (strict <): ties keep earlier-processed entry
__device__ __forceinline__ void ins3(float* lu, int* li, float u, int n) {
    if (u < lu[0]) {
        lu[2] = lu[1]; li[2] = li[1];
        lu[1] = lu[0]; li[1] = li[0];
        lu[0] = u;     li[0] = n;
    } else if (u < lu[1]) {
        lu[2] = lu[1]; li[2] = li[1];
        lu[1] = u;     li[1] = n;
    } else if (u < lu[2]) {
        lu[2] = u;     li[2] = n;
    }
}

__device__ __forceinline__ uint32_t smem_u32(const void* p) {
    uint32_t a;
    asm("{ .reg .u64 t; cvta.to.shared.u64 t, %1; cvt.u32.u64 %0, t; }"
        : "=r"(a) : "l"(p));
    return a;
}

// stage one 32-code fp16 B tile (16KB) into smem buffer via cp.async
__device__ __forceinline__ void stage_tile(uint32_t sbB, int buf, int n0, int tid) {
    uint32_t bb = sbB + (buf ? SBB : 0);
    #pragma unroll
    for (int it = 0; it < 4; ++it) {
        int i = tid + it * 256;              // 0..1023 16B chunks
        int n = i >> 5;
        int q = i & 31;
        const __half* src = g_ch + (size_t)(n0 + n) * C_ + q * 8;
        uint32_t dst = bb + (uint32_t)(n * 528 + q * 16);
        asm volatile("cp.async.cg.shared.global [%0], [%1], 16;"
                     :: "r"(dst), "l"(src) : "memory");
    }
}

// ---------------------------------------------------------------------------
// main: 128 pixels x 1024 codes per CTA, fp16 HMMA (R10 mainloop, best
// measured) + FUSED output epilogue (k_output's transpose pattern, 4x32
// pixel chunks). Flagged pixels get provisional outputs; rescues patch.
// ---------------------------------------------------------------------------
__global__ __launch_bounds__(256, 2) void k_main(const float* __restrict__ z,
                                                 const float* __restrict__ cb,
                                                 float* __restrict__ out,
                                                 long long out_size) {
    extern __shared__ __align__(16) char smem[];
    uint32_t* SA = (uint32_t*)smem;                       // [128][132] words
    float* s_eeh = (float*)(smem + OFF_EEH);
    float* SU    = (float*)(smem + OFF_U3);               // [2][128][3]
    int*   SI    = (int*)(smem + OFF_I3);

    const int tid  = threadIdx.x;
    const int lane = tid & 31;
    const int warp = tid >> 5;
    const int g    = lane >> 2;
    const int tc   = lane & 3;
    const int wm   = warp & 3;      // 4 x 32 M rows
    const int wn   = warp >> 2;     // 2 x 16 N cols
    const int m0   = blockIdx.x * 128;
    const uint32_t sbA = smem_u32(smem);
    const uint32_t sbB = smem_u32(smem + OFF_B);

    stage_tile(sbB, 0, 0, tid);
    asm volatile("cp.async.commit_group;" ::: "memory");

    for (int i = tid; i < NC_; i += 256)
        s_eeh[i] = __fmul_rn(0.5f, g_ee[i]);

    // ---- A: 128 pixels x 256 ch from NCHW z -> fp16, smem ----
    {
        int m   = tid & 127;
        int cp0 = tid >> 7;
        const float* zb = z + ((size_t)(m0 >> 10) * 256) * 1024 + (m0 & 1023) + m;
        uint32_t* arow = SA + (size_t)m * AW;
        #pragma unroll 4
        for (int cp = cp0; cp < 128; cp += 2) {
            float v0 = zb[(size_t)(2 * cp) << 10];
            float v1 = zb[(size_t)(2 * cp + 1) << 10];
            __half h0 = __float2half_rn(v0);
            __half h1 = __float2half_rn(v1);
            arow[cp] = (uint32_t)__half_as_ushort(h0) |
                       ((uint32_t)__half_as_ushort(h1) << 16);
        }
    }
    __syncthreads();

    float bu[4][3];
    int   bi[4][3];
    #pragma unroll
    for (int j = 0; j < 4; ++j) {
        bu[j][0] = bu[j][1] = bu[j][2] = 3.4e38f;
        bi[j][0] = bi[j][1] = bi[j][2] = 0;
    }

    // ldmatrix per-lane base addresses
    const uint32_t aA0 = sbA + (uint32_t)((wm * 32 + (lane & 15)) * AW) * 4
                             + (uint32_t)(lane >> 4) * 16;
    const uint32_t aA1 = aA0 + 16 * AW * 4;
    const uint32_t aBr = (uint32_t)((wn * 16 + ((lane >> 4) << 3) + (lane & 7))
                                    * AW) * 4
                       + (uint32_t)((lane >> 3) & 1) * 16;

    for (int nt = 0; nt < 32; ++nt) {
        asm volatile("cp.async.wait_group 0;" ::: "memory");
        __syncthreads();                       // tile nt visible; reuse safe

        if (nt < 31) {
            stage_tile(sbB, (nt + 1) & 1, (nt + 1) * 32, tid);
            asm volatile("cp.async.commit_group;" ::: "memory");
        }

        const uint32_t aB = sbB + (uint32_t)(nt & 1) * SBB + aBr;

        float acc[2][2][4];
        #pragma unroll
        for (int a = 0; a < 2; ++a)
            #pragma unroll
            for (int b = 0; b < 2; ++b)
                #pragma unroll
                for (int r = 0; r < 4; ++r) acc[a][b][r] = 0.f;

        #pragma unroll
        for (int kk = 0; kk < 16; ++kk) {
            uint32_t b00, b10, b01, b11;
            asm volatile(
                "ldmatrix.sync.aligned.m8n8.x4.shared.b16 {%0,%1,%2,%3}, [%4];"
                : "=r"(b00), "=r"(b10), "=r"(b01), "=r"(b11)
                : "r"(aB + kk * 32));
            uint32_t a0, a1, a2, a3;
            asm volatile(
                "ldmatrix.sync.aligned.m8n8.x4.shared.b16 {%0,%1,%2,%3}, [%4];"
                : "=r"(a0), "=r"(a1), "=r"(a2), "=r"(a3)
                : "r"(aA0 + kk * 32));
            mma_f16(acc[0][0], a0, a1, a2, a3, b00, b10);
            mma_f16(acc[0][1], a0, a1, a2, a3, b01, b11);
            asm volatile(
                "ldmatrix.sync.aligned.m8n8.x4.shared.b16 {%0,%1,%2,%3}, [%4];"
                : "=r"(a0), "=r"(a1), "=r"(a2), "=r"(a3)
                : "r"(aA1 + kk * 32));
            mma_f16(acc[1][0], a0, a1, a2, a3, b00, b10);
            mma_f16(acc[1][1], a0, a1, a2, a3, b01, b11);
        }

        // ---- epilogue: u = ee/2 - mm, top-3 insert (ascending n) ----
        #pragma unroll
        for (int mt = 0; mt < 2; ++mt)
            #pragma unroll
            for (int ntl = 0; ntl < 2; ++ntl)
                #pragma unroll
                for (int r = 0; r < 4; ++r) {
                    int lr = mt * 2 + (r >> 1);
                    int n  = nt * 32 + wn * 16 + ntl * 8 + tc * 2 + (r & 1);
                    float u = __fsub_rn(s_eeh[n], acc[mt][ntl][r]);
                    ins3(bu[lr], bi[lr], u, n);
                }
    }

    // ---- top-3 reduction: tc lanes via shfl, then two wn warps via smem ----
    #pragma unroll
    for (int j = 0; j < 4; ++j) {
        #pragma unroll
        for (int off = 1; off <= 2; off <<= 1) {
            float ou[3]; int oi[3];
            #pragma unroll
            for (int k = 0; k < 3; ++k) {
                ou[k] = __shfl_xor_sync(0xffffffffu, bu[j][k], off);
                oi[k] = __shfl_xor_sync(0xffffffffu, bi[j][k], off);
            }
            #pragma unroll
            for (int k = 0; k < 3; ++k) ins3(bu[j], bi[j], ou[k], oi[k]);
        }
        if (tc == 0) {
            int row = wm * 32 + (j >> 1) * 16 + (j & 1) * 8 + g;
            #pragma unroll
            for (int k = 0; k < 3; ++k) {
                SU[(wn * 128 + row) * 3 + k] = bu[j][k];
                SI[(wn * 128 + row) * 3 + k] = bi[j][k];
            }
        }
    }
    __syncthreads();

    int* s_idx = (int*)(smem + OFF_B);     // alias: SB dead after mainloop
    if (tid < 128) {
        float lu[3]; int li[3];
        #pragma unroll
        for (int k = 0; k < 3; ++k) {
            lu[k] = SU[tid * 3 + k];
            li[k] = SI[tid * 3 + k];
        }
        #pragma unroll
        for (int k = 0; k < 3; ++k)
            ins3(lu, li, SU[(128 + tid) * 3 + k], SI[(128 + tid) * 3 + k]);

        int p = m0 + tid;
        g_idx[p] = li[0];
        s_idx[tid] = li[0];
        long long oi2 = 2LL * NCHW_ + p;
        if (oi2 < out_size) out[oi2] = (float)li[0];   // provisional idx
        float gap2 = __fsub_rn(lu[1], lu[0]);
        float gap3 = __fsub_rn(lu[2], lu[0]);
        if (gap3 < TIE_T) {
            int pos = atomicAdd(&g_nB, 1);
            g_flB[pos] = p;
        } else if (gap2 < TIE_T) {
            int pos = atomicAdd(&g_nA, 1);
            g_flA[pos] = make_int4(p, li[0], li[1], li[2]);
        }
    }
    __syncthreads();

    // ---- fused output: 4 chunks of 32 pixels (k_output pattern verbatim) ----
    float (*tile)[33] = (float (*)[33])smem;   // 256x33 f32, aliases dead SA
    const int bb  = m0 >> 10;
    const int hw0 = m0 & 1023;
    for (int cc = 0; cc < 4; ++cc) {
        __syncthreads();
        #pragma unroll 8
        for (int w = 0; w < 32; ++w)
            tile[tid][w] = cb[(size_t)s_idx[cc * 32 + w] * C_ + tid];
        __syncthreads();
        long long obase = (long long)bb * 262144 + hw0 + cc * 32;
        int w = tid & 31;
        #pragma unroll 8
        for (int it = 0; it < 32; ++it) {
            int c = it * 8 + (tid >> 5);
            float q = tile[c][w];
            long long o = obase + (long long)c * 1024 + w;
            float zv = z[o];
            float st = __fadd_rn(__fsub_rn(q, zv), zv);
            if (o < out_size) out[o] = q;
            if (NCHW_ + o < out_size) out[NCHW_ + o] = st;
        }
    }
}

// ---------------------------------------------------------------------------
// rescue A: exact fp32 distances for <=3 candidates; patches outputs on change.
// ---------------------------------------------------------------------------
__global__ __launch_bounds__(128) void k_rescueA(const float* __restrict__ z,
                                                 const float* __restrict__ cb,
                                                 float* __restrict__ out,
                                                 long long out_size) {
    int lane = threadIdx.x & 31;
    int warp = threadIdx.x >> 5;
    int total = g_nA;

    for (int it = blockIdx.x * 4 + warp; it < total; it += gridDim.x * 4) {
        int4 f = g_flA[it];
        int p = f.x;
        const float* zp = z + (size_t)(p >> 10) * (C_ * 1024) + (p & 1023);

        float zv[8];
        #pragma unroll
        for (int j = 0; j < 8; ++j)
            zv[j] = zp[(size_t)(lane + 32 * j) * 1024];

        float zz = 0.f;
        #pragma unroll
        for (int j = 0; j < 8; ++j) zz = fmaf(zv[j], zv[j], zz);
        #pragma unroll
        for (int o = 16; o; o >>= 1) zz += __shfl_xor_sync(0xffffffffu, zz, o);

        int cand[3] = { f.y, f.z, f.w };
        unsigned long long best = ~0ULL;
        #pragma unroll
        for (int c = 0; c < 3; ++c) {
            int n = cand[c];
            const float* cr = cb + (size_t)n * C_;
            float a = 0.f;
            #pragma unroll
            for (int jj = 0; jj < 8; ++jj)
                a = fmaf(cr[lane + 32 * jj], zv[jj], a);
            #pragma unroll
            for (int o = 16; o; o >>= 1)
                a += __shfl_xor_sync(0xffffffffu, a, o);
            float d = __fsub_rn(__fadd_rn(zz, g_ee[n]), __fmul_rn(2.0f, a));
            uint32_t bits = __float_as_uint(d);
            bits = (bits & 0x80000000u) ? ~bits : (bits | 0x80000000u);
            unsigned long long pk =
                ((unsigned long long)bits << 32) | (unsigned)n;
            if (pk < best) best = pk;
        }
        int fin = (int)(best & 0xFFFFFFFFu);   // uniform across lanes
        if (!lane) g_idx[p] = fin;
        if (fin != f.y) {                      // patch outputs
            const float* cr = cb + (size_t)fin * C_;
            long long ob = (long long)(p >> 10) * 262144 + (p & 1023);
            #pragma unroll
            for (int j = 0; j < 8; ++j) {
                int c = lane + 32 * j;
                float q = cr[c];
                float st = __fadd_rn(__fsub_rn(q, zv[j]), zv[j]);
                long long o = ob + (long long)c * 1024;
                if (o < out_size) out[o] = q;
                if (NCHW_ + o < out_size) out[NCHW_ + o] = st;
            }
            long long oi2 = 2LL * NCHW_ + p;
            if (!lane && oi2 < out_size) out[oi2] = (float)fin;
        }
    }
}

// ---------------------------------------------------------------------------
// rescue B: full exact sweep for rare 3-in-window pixels; patches outputs.
// ---------------------------------------------------------------------------
__global__ __launch_bounds__(256) void k_rescueB(const float* __restrict__ z,
                                                 const float* __restrict__ cb,
                                                 float* __restrict__ out,
                                                 long long out_size) {
    __shared__ float zr[8][257];
    __shared__ float zz8[8];
    __shared__ unsigned long long best8[8];
    __shared__ int pix8[8];
    __shared__ int fin8[8];
    __shared__ int chg8[8];
    __shared__ int s_np;

    int tid = threadIdx.x, lane = tid & 31, warp = tid >> 5;

    for (int base = blockIdx.x * 8;; base += gridDim.x * 8) {
        if (tid == 0) s_np = g_nB - base;
        __syncthreads();
        int np = s_np;
        if (np <= 0) break;
        if (np > 8) np = 8;

        if (tid < 8) {
            best8[tid] = ~0ULL;
            pix8[tid] = (tid < np) ? g_flB[base + tid] : 0;
        }
        __syncthreads();

        for (int j = 0; j < np; ++j) {
            int p = pix8[j];
            zr[j][tid] = z[(size_t)(p >> 10) * (C_ * 1024) +
                           (size_t)tid * 1024 + (p & 1023)];
        }
        __syncthreads();

        if (warp < np) {
            float a = 0.f;
            #pragma unroll
            for (int k = lane; k < C_; k += 32) {
                float v = zr[warp][k];
                a = fmaf(v, v, a);
            }
            #pragma unroll
            for (int o = 16; o; o >>= 1) a += __shfl_xor_sync(0xffffffffu, a, o);
            if (!lane) zz8[warp] = a;
        }
        __syncthreads();

        float acc[8][4];
        #pragma unroll
        for (int j = 0; j < 8; ++j)
            #pragma unroll
            for (int c = 0; c < 4; ++c) acc[j][c] = 0.f;

        const float* cbt = g_cbT + 4 * tid;
        #pragma unroll 8
        for (int k = 0; k < C_; ++k) {
            float4 cv = *(const float4*)(cbt + (size_t)k * NC_);
            #pragma unroll
            for (int j = 0; j < 8; ++j) {
                float zvv = zr[j][k];
                acc[j][0] = fmaf(zvv, cv.x, acc[j][0]);
                acc[j][1] = fmaf(zvv, cv.y, acc[j][1]);
                acc[j][2] = fmaf(zvv, cv.z, acc[j][2]);
                acc[j][3] = fmaf(zvv, cv.w, acc[j][3]);
            }
        }

        float een[4];
        #pragma unroll
        for (int c = 0; c < 4; ++c) een[c] = g_ee[4 * tid + c];

        for (int j = 0; j < np; ++j) {
            unsigned long long lb = ~0ULL;
            float zzj = zz8[j];
            #pragma unroll
            for (int c = 0; c < 4; ++c) {
                float d = __fsub_rn(__fadd_rn(zzj, een[c]),
                                    __fmul_rn(2.0f, acc[j][c]));
                uint32_t bits = __float_as_uint(d);
                bits = (bits & 0x80000000u) ? ~bits : (bits | 0x80000000u);
                unsigned long long pk =
                    ((unsigned long long)bits << 32) | (unsigned)(4 * tid + c);
                if (pk < lb) lb = pk;
            }
            #pragma unroll
            for (int o = 16; o; o >>= 1) {
                unsigned long long ov = __shfl_xor_sync(0xffffffffu, lb, o);
                if (ov < lb) lb = ov;
            }
            if (!lane) atomicMin(&best8[j], lb);
        }
        __syncthreads();
        if (tid < np) {
            int p = pix8[tid];
            int fin = (int)(best8[tid] & 0xFFFFFFFFu);
            int prov = g_idx[p];
            g_idx[p] = fin;
            fin8[tid] = fin;
            chg8[tid] = (fin != prov);
            if (fin != prov) {
                long long oi2 = 2LL * NCHW_ + p;
                if (oi2 < out_size) out[oi2] = (float)fin;
            }
        }
        __syncthreads();
        if (warp < np && chg8[warp]) {         // patch outputs, 1 warp/pixel
            int p = pix8[warp];
            int fin = fin8[warp];
            const float* cr = cb + (size_t)fin * C_;
            long long ob = (long long)(p >> 10) * 262144 + (p & 1023);
            #pragma unroll
            for (int j = 0; j < 8; ++j) {
                int c = lane + 32 * j;
                float q = cr[c];
                float zvv = zr[warp][c];
                float st = __fadd_rn(__fsub_rn(q, zvv), zvv);
                long long o = ob + (long long)c * 1024;
                if (o < out_size) out[o] = q;
                if (NCHW_ + o < out_size) out[NCHW_ + o] = st;
            }
        }
        __syncthreads();
    }
}

// ---------------------------------------------------------------------------
extern "C" void kernel_launch(void* const* d_in, const int* in_sizes, int n_in,
                              void* d_out, int out_size) {
    const float* z  = (const float*)d_in[0];   // (64,256,32,32) f32
    const float* cb = (const float*)d_in[1];   // (1024,256) f32
    float* out = (float*)d_out;
    long long osz = (long long)out_size;

    cudaFuncSetAttribute(k_main, cudaFuncAttributeMaxDynamicSharedMemorySize,
                         SMEM_DYN);

    k_cbsplit<<<NC_ / 8, 256>>>(cb);
    k_main<<<P_ / 128, 256, SMEM_DYN>>>(z, cb, out, osz);
    k_rescueA<<<1024, 128>>>(z, cb, out, osz);
    k_rescueB<<<256, 256>>>(z, cb, out, osz);
}

// round 16
// speedup vs baseline: 1.0303x; 1.0303x over previous
#include <cuda_runtime.h>
#include <cuda_fp16.h>
#include <cstdint>

#define C_    256
#define P_    65536
#define NC_   1024
#define NCHW_ 16777216

// ---- device scratch -------------------------------------------------------
__device__ __half g_ch[NC_ * C_];          // codebook fp16, K-major
__device__ float g_cbT[C_ * NC_];          // codebook transposed [k][n] f32
__device__ float g_ee[NC_];
__device__ int   g_idx[P_];
__device__ int   g_nA, g_nB;
__device__ int4  g_flA[P_];                // (pixel, cand0, cand1, cand2)
__device__ int   g_flB[P_];
__device__ unsigned long long g_bestB[P_];

// ---- k_main smem layout (BM=128, BN=32, double-buffered B) ----------------
#define AW       132                    // words per row (132%32==4 -> conflict-free)
#define SBB      16896                  // one B buffer: 32 * 132 * 4
#define OFF_B    67584                  // SA: 128 x 132 words
#define OFF_EEH  101376                 // 1024 f32
#define OFF_U3   105472                 // float[2][128][3]
#define OFF_I3   108544                 // int[2][128][3]
#define SMEM_DYN 111616                 // ~109KB -> 2 CTAs/SM

#define TIE_T    6.5e-5f                // 3.1e-5 ref-jitter bound + 6.5 sigma

// ---------------------------------------------------------------------------
// codebook -> fp16 + transpose + exact ||e||^2 ; resets flag counters
__global__ void k_cbsplit(const float* __restrict__ cb) {
    if (blockIdx.x == 0 && threadIdx.x == 0) { g_nA = 0; g_nB = 0; }
    int gw   = (blockIdx.x * blockDim.x + threadIdx.x) >> 5;
    int lane = threadIdx.x & 31;
    if (gw >= NC_) return;
    const float* r = cb + (size_t)gw * C_;
    float acc = 0.f;
    #pragma unroll
    for (int k = lane; k < C_; k += 32) {
        float v = r[k];
        acc = fmaf(v, v, acc);
        g_ch[(size_t)gw * C_ + k] = __float2half_rn(v);
        g_cbT[(size_t)k * NC_ + gw] = v;
    }
    #pragma unroll
    for (int o = 16; o; o >>= 1) acc += __shfl_xor_sync(0xffffffffu, acc, o);
    if (!lane) g_ee[gw] = acc;
}

// ---------------------------------------------------------------------------
__device__ __forceinline__ void mma_f16(float* c, uint32_t a0, uint32_t a1,
                                        uint32_t a2, uint32_t a3,
                                        uint32_t b0, uint32_t b1) {
    asm volatile(
        "mma.sync.aligned.m16n8k16.row.col.f32.f16.f16.f32 "
        "{%0,%1,%2,%3}, {%4,%5,%6,%7}, {%8,%9}, {%0,%1,%2,%3};"
        : "+f"(c[0]), "+f"(c[1]), "+f"(c[2]), "+f"(c[3])
        : "r"(a0), "r"(a1), "r"(a2), "r"(a3), "r"(b0), "r"(b1));
}

// stable 3-slot sorted insert (strict <): ties keep earlier-processed entry
__device__ __forceinline__ void ins3(float* lu, int* li, float u, int n) {
    if (u < lu[0]) {
        lu[2] = lu[1]; li[2] = li[1];
        lu[1] = lu[0]; li[1] = li[0];
        lu[0] = u;     li[0] = n;
    } else if (u < lu[1]) {
        lu[2] = lu[1]; li[2] = li[1];
        lu[1] = u;     li[1] = n;
    } else if (u < lu[2]) {
        lu[2] = u;     li[2] = n;
    }
}

__device__ __forceinline__ uint32_t smem_u32(const void* p) {
    uint32_t a;
    asm("{ .reg .u64 t; cvta.to.shared.u64 t, %1; cvt.u32.u64 %0, t; }"
        : "=r"(a) : "l"(p));
    return a;
}

// stage one 32-code fp16 B tile (16KB) into smem buffer via cp.async
__device__ __forceinline__ void stage_tile(uint32_t sbB, int buf, int n0, int tid) {
    uint32_t bb = sbB + (buf ? SBB : 0);
    #pragma unroll
    for (int it = 0; it < 4; ++it) {
        int i = tid + it * 256;              // 0..1023 16B chunks
        int n = i >> 5;
        int q = i & 31;
        const __half* src = g_ch + (size_t)(n0 + n) * C_ + q * 8;
        uint32_t dst = bb + (uint32_t)(n * 528 + q * 16);
        asm volatile("cp.async.cg.shared.global [%0], [%1], 16;"
                     :: "r"(dst), "l"(src) : "memory");
    }
}

// ---------------------------------------------------------------------------
// main: 128 pixels x 1024 codes per CTA, fp16 HMMA with ldmatrix fragment
// feed (R10/R14 configuration: best measured, 193.7us).
// ---------------------------------------------------------------------------
__global__ __launch_bounds__(256, 2) void k_main(const float* __restrict__ z) {
    extern __shared__ __align__(16) char smem[];
    uint32_t* SA = (uint32_t*)smem;                       // [128][132] words
    float* s_eeh = (float*)(smem + OFF_EEH);
    float* SU    = (float*)(smem + OFF_U3);               // [2][128][3]
    int*   SI    = (int*)(smem + OFF_I3);

    const int tid  = threadIdx.x;
    const int lane = tid & 31;
    const int warp = tid >> 5;
    const int g    = lane >> 2;
    const int tc   = lane & 3;
    const int wm   = warp & 3;      // 4 x 32 M rows
    const int wn   = warp >> 2;     // 2 x 16 N cols
    const int m0   = blockIdx.x * 128;
    const uint32_t sbA = smem_u32(smem);
    const uint32_t sbB = smem_u32(smem + OFF_B);

    stage_tile(sbB, 0, 0, tid);
    asm volatile("cp.async.commit_group;" ::: "memory");

    for (int i = tid; i < NC_; i += 256)
        s_eeh[i] = __fmul_rn(0.5f, g_ee[i]);

    // ---- A: 128 pixels x 256 ch from NCHW z -> fp16, smem ----
    {
        int m   = tid & 127;
        int cp0 = tid >> 7;
        const float* zb = z + ((size_t)(m0 >> 10) * 256) * 1024 + (m0 & 1023) + m;
        uint32_t* arow = SA + (size_t)m * AW;
        #pragma unroll 4
        for (int cp = cp0; cp < 128; cp += 2) {
            float v0 = zb[(size_t)(2 * cp) << 10];
            float v1 = zb[(size_t)(2 * cp + 1) << 10];
            __half h0 = __float2half_rn(v0);
            __half h1 = __float2half_rn(v1);
            arow[cp] = (uint32_t)__half_as_ushort(h0) |
                       ((uint32_t)__half_as_ushort(h1) << 16);
        }
    }
    __syncthreads();

    float bu[4][3];
    int   bi[4][3];
    #pragma unroll
    for (int j = 0; j < 4; ++j) {
        bu[j][0] = bu[j][1] = bu[j][2] = 3.4e38f;
        bi[j][0] = bi[j][1] = bi[j][2] = 0;
    }

    // ldmatrix per-lane base addresses
    const uint32_t aA0 = sbA + (uint32_t)((wm * 32 + (lane & 15)) * AW) * 4
                             + (uint32_t)(lane >> 4) * 16;
    const uint32_t aA1 = aA0 + 16 * AW * 4;
    const uint32_t aBr = (uint32_t)((wn * 16 + ((lane >> 4) << 3) + (lane & 7))
                                    * AW) * 4
                       + (uint32_t)((lane >> 3) & 1) * 16;

    for (int nt = 0; nt < 32; ++nt) {
        asm volatile("cp.async.wait_group 0;" ::: "memory");
        __syncthreads();                       // tile nt visible; reuse safe

        if (nt < 31) {
            stage_tile(sbB, (nt + 1) & 1, (nt + 1) * 32, tid);
            asm volatile("cp.async.commit_group;" ::: "memory");
        }

        const uint32_t aB = sbB + (uint32_t)(nt & 1) * SBB + aBr;

        float acc[2][2][4];
        #pragma unroll
        for (int a = 0; a < 2; ++a)
            #pragma unroll
            for (int b = 0; b < 2; ++b)
                #pragma unroll
                for (int r = 0; r < 4; ++r) acc[a][b][r] = 0.f;

        #pragma unroll
        for (int kk = 0; kk < 16; ++kk) {
            uint32_t b00, b10, b01, b11;
            asm volatile(
                "ldmatrix.sync.aligned.m8n8.x4.shared.b16 {%0,%1,%2,%3}, [%4];"
                : "=r"(b00), "=r"(b10), "=r"(b01), "=r"(b11)
                : "r"(aB + kk * 32));
            uint32_t a0, a1, a2, a3;
            asm volatile(
                "ldmatrix.sync.aligned.m8n8.x4.shared.b16 {%0,%1,%2,%3}, [%4];"
                : "=r"(a0), "=r"(a1), "=r"(a2), "=r"(a3)
                : "r"(aA0 + kk * 32));
            mma_f16(acc[0][0], a0, a1, a2, a3, b00, b10);
            mma_f16(acc[0][1], a0, a1, a2, a3, b01, b11);
            asm volatile(
                "ldmatrix.sync.aligned.m8n8.x4.shared.b16 {%0,%1,%2,%3}, [%4];"
                : "=r"(a0), "=r"(a1), "=r"(a2), "=r"(a3)
                : "r"(aA1 + kk * 32));
            mma_f16(acc[1][0], a0, a1, a2, a3, b00, b10);
            mma_f16(acc[1][1], a0, a1, a2, a3, b01, b11);
        }

        // ---- epilogue: u = ee/2 - mm, top-3 insert (ascending n) ----
        #pragma unroll
        for (int mt = 0; mt < 2; ++mt)
            #pragma unroll
            for (int ntl = 0; ntl < 2; ++ntl)
                #pragma unroll
                for (int r = 0; r < 4; ++r) {
                    int lr = mt * 2 + (r >> 1);
                    int n  = nt * 32 + wn * 16 + ntl * 8 + tc * 2 + (r & 1);
                    float u = __fsub_rn(s_eeh[n], acc[mt][ntl][r]);
                    ins3(bu[lr], bi[lr], u, n);
                }
    }

    // ---- top-3 reduction: tc lanes via shfl, then two wn warps via smem ----
    #pragma unroll
    for (int j = 0; j < 4; ++j) {
        #pragma unroll
        for (int off = 1; off <= 2; off <<= 1) {
            float ou[3]; int oi[3];
            #pragma unroll
            for (int k = 0; k < 3; ++k) {
                ou[k] = __shfl_xor_sync(0xffffffffu, bu[j][k], off);
                oi[k] = __shfl_xor_sync(0xffffffffu, bi[j][k], off);
            }
            #pragma unroll
            for (int k = 0; k < 3; ++k) ins3(bu[j], bi[j], ou[k], oi[k]);
        }
        if (tc == 0) {
            int row = wm * 32 + (j >> 1) * 16 + (j & 1) * 8 + g;
            #pragma unroll
            for (int k = 0; k < 3; ++k) {
                SU[(wn * 128 + row) * 3 + k] = bu[j][k];
                SI[(wn * 128 + row) * 3 + k] = bi[j][k];
            }
        }
    }
    __syncthreads();

    if (tid < 128) {
        float lu[3]; int li[3];
        #pragma unroll
        for (int k = 0; k < 3; ++k) {
            lu[k] = SU[tid * 3 + k];
            li[k] = SI[tid * 3 + k];
        }
        #pragma unroll
        for (int k = 0; k < 3; ++k)
            ins3(lu, li, SU[(128 + tid) * 3 + k], SI[(128 + tid) * 3 + k]);

        int p = m0 + tid;
        g_idx[p] = li[0];
        float gap2 = __fsub_rn(lu[1], lu[0]);
        float gap3 = __fsub_rn(lu[2], lu[0]);
        if (gap3 < TIE_T) {
            int pos = atomicAdd(&g_nB, 1);
            g_bestB[pos] = 0xFFFFFFFFFFFFFFFFull;
            g_flB[pos] = p;
        } else if (gap2 < TIE_T) {
            int pos = atomicAdd(&g_nA, 1);
            g_flA[pos] = make_int4(p, li[0], li[1], li[2]);
        }
    }
}

// ---------------------------------------------------------------------------
// rescue A: exact fp32 distances for <=3 candidate codes per flagged pixel.
// ---------------------------------------------------------------------------
__global__ __launch_bounds__(128) void k_rescueA(const float* __restrict__ z,
                                                 const float* __restrict__ cb) {
    int lane = threadIdx.x & 31;
    int warp = threadIdx.x >> 5;
    int total = g_nA;

    for (int it = blockIdx.x * 4 + warp; it < total; it += gridDim.x * 4) {
        int4 f = g_flA[it];
        int p = f.x;
        const float* zp = z + (size_t)(p >> 10) * (C_ * 1024) + (p & 1023);

        float zv[8];
        #pragma unroll
        for (int j = 0; j < 8; ++j)
            zv[j] = zp[(size_t)(lane + 32 * j) * 1024];

        float zz = 0.f;
        #pragma unroll
        for (int j = 0; j < 8; ++j) zz = fmaf(zv[j], zv[j], zz);
        #pragma unroll
        for (int o = 16; o; o >>= 1) zz += __shfl_xor_sync(0xffffffffu, zz, o);

        int cand[3] = { f.y, f.z, f.w };
        unsigned long long best = ~0ULL;
        #pragma unroll
        for (int c = 0; c < 3; ++c) {
            int n = cand[c];
            const float* cr = cb + (size_t)n * C_;
            float a = 0.f;
            #pragma unroll
            for (int jj = 0; jj < 8; ++jj)
                a = fmaf(cr[lane + 32 * jj], zv[jj], a);
            #pragma unroll
            for (int o = 16; o; o >>= 1)
                a += __shfl_xor_sync(0xffffffffu, a, o);
            float d = __fsub_rn(__fadd_rn(zz, g_ee[n]), __fmul_rn(2.0f, a));
            uint32_t bits = __float_as_uint(d);
            bits = (bits & 0x80000000u) ? ~bits : (bits | 0x80000000u);
            unsigned long long pk =
                ((unsigned long long)bits << 32) | (unsigned)n;
            if (pk < best) best = pk;
        }
        if (!lane) g_idx[p] = (int)(best & 0xFFFFFFFFu);
    }
}

// ---------------------------------------------------------------------------
// rescue B1: parallel exact sweep. One warp per (B-pixel, 128-code chunk):
// lane owns 4 codes; k-loop reads 4 coalesced cbT lines per k with z
// broadcast via shfl. Exact d + packed-u64 atomicMin -> global argmin with
// first-index tie-break.
// ---------------------------------------------------------------------------
__global__ __launch_bounds__(256) void k_rescueB1(const float* __restrict__ z) {
    int lane  = threadIdx.x & 31;
    int gwarp = (blockIdx.x * blockDim.x + threadIdx.x) >> 5;
    int nwarp = (gridDim.x * blockDim.x) >> 5;
    int total = g_nB * 8;

    for (int item = gwarp; item < total; item += nwarp) {
        int pos   = item >> 3;
        int chunk = item & 7;
        int p = g_flB[pos];
        const float* zp = z + (size_t)(p >> 10) * (C_ * 1024) + (p & 1023);

        float zv[8];
        #pragma unroll
        for (int j = 0; j < 8; ++j)
            zv[j] = zp[(size_t)(lane + 32 * j) * 1024];

        float zz = 0.f;
        #pragma unroll
        for (int j = 0; j < 8; ++j) zz = fmaf(zv[j], zv[j], zz);
        #pragma unroll
        for (int o = 16; o; o >>= 1) zz += __shfl_xor_sync(0xffffffffu, zz, o);

        const int n0 = chunk * 128 + lane;
        float acc[4] = { 0.f, 0.f, 0.f, 0.f };
        const float* cbt = g_cbT + n0;
        #pragma unroll
        for (int j = 0; j < 8; ++j) {
            #pragma unroll 8
            for (int l = 0; l < 32; ++l) {
                float zk = __shfl_sync(0xffffffffu, zv[j], l);
                const float* row = cbt + (size_t)(j * 32 + l) * NC_;
                acc[0] = fmaf(zk, row[0],  acc[0]);
                acc[1] = fmaf(zk, row[32], acc[1]);
                acc[2] = fmaf(zk, row[64], acc[2]);
                acc[3] = fmaf(zk, row[96], acc[3]);
            }
        }

        unsigned long long lb = ~0ULL;
        #pragma unroll
        for (int c = 0; c < 4; ++c) {
            int n = n0 + c * 32;
            float d = __fsub_rn(__fadd_rn(zz, g_ee[n]),
                                __fmul_rn(2.0f, acc[c]));
            uint32_t bits = __float_as_uint(d);
            bits = (bits & 0x80000000u) ? ~bits : (bits | 0x80000000u);
            unsigned long long pk =
                ((unsigned long long)bits << 32) | (unsigned)n;
            if (pk < lb) lb = pk;
        }
        #pragma unroll
        for (int o = 16; o; o >>= 1) {
            unsigned long long ov = __shfl_xor_sync(0xffffffffu, lb, o);
            if (ov < lb) lb = ov;
        }
        if (!lane) atomicMin(&g_bestB[pos], lb);
    }
}

// rescue B2: commit winners to g_idx before the output pass.
__global__ void k_rescueB2() {
    int i = blockIdx.x * blockDim.x + threadIdx.x;
    int total = g_nB;
    for (; i < total; i += gridDim.x * blockDim.x)
        g_idx[g_flB[i]] = (int)(g_bestB[i] & 0xFFFFFFFFu);
}

// ---------------------------------------------------------------------------
// outputs via smem transpose; straight_through = fl(fl(q - z) + z) exactly.
// ---------------------------------------------------------------------------
__global__ __launch_bounds__(256) void k_output(const float* __restrict__ cb,
                                                const float* __restrict__ zin,
                                                float* __restrict__ out,
                                                long long out_size) {
    __shared__ float tile[256][33];
    __shared__ int idxs[32];
    int bh = blockIdx.x;                     // b*32 + h
    int b = bh >> 5, h = bh & 31;
    int tid = threadIdx.x;

    if (tid < 32) idxs[tid] = g_idx[bh * 32 + tid];
    __syncthreads();

    #pragma unroll 8
    for (int w = 0; w < 32; ++w)
        tile[tid][w] = cb[(size_t)idxs[w] * C_ + tid];
    __syncthreads();

    long long obase = ((long long)b * 256) * 1024 + (long long)h * 32;
    int w = tid & 31;
    #pragma unroll 8
    for (int it = 0; it < 32; ++it) {
        int c = it * 8 + (tid >> 5);
        float q = tile[c][w];
        long long o = obase + (long long)c * 1024 + w;
        float zv = zin[o];
        float st = __fadd_rn(__fsub_rn(q, zv), zv);
        if (o < out_size) out[o] = q;
        if (NCHW_ + o < out_size) out[NCHW_ + o] = st;
    }
    if (tid < 32) {
        long long o = 2LL * NCHW_ + bh * 32 + tid;
        if (o < out_size) out[o] = (float)idxs[tid];
    }
}

// ---------------------------------------------------------------------------
extern "C" void kernel_launch(void* const* d_in, const int* in_sizes, int n_in,
                              void* d_out, int out_size) {
    const float* z  = (const float*)d_in[0];   // (64,256,32,32) f32
    const float* cb = (const float*)d_in[1];   // (1024,256) f32
    float* out = (float*)d_out;

    cudaFuncSetAttribute(k_main, cudaFuncAttributeMaxDynamicSharedMemorySize,
                         SMEM_DYN);

    // 4th launch (k_rescueB1) lands in the ncu capture window
    k_cbsplit<<<NC_ / 8, 256>>>(cb);
    k_main<<<P_ / 128, 256, SMEM_DYN>>>(z);
    k_rescueA<<<1024, 128>>>(z, cb);
    k_rescueB1<<<256, 256>>>(z);
    k_rescueB2<<<64, 256>>>();
    k_output<<<2048, 256>>>(cb, z, out, (long long)out_size);
}

// round 17
// speedup vs baseline: 1.2117x; 1.1761x over previous
#include <cuda_runtime.h>
#include <cuda_fp16.h>
#include <cstdint>

#define C_    256
#define P_    65536
#define NC_   1024
#define NCHW_ 16777216

// ---- device scratch -------------------------------------------------------
__device__ __half g_ch[NC_ * C_];          // codebook fp16, K-major
__device__ float g_ee[NC_];
__device__ int   g_idx[P_];
__device__ int   g_nA, g_nB;
__device__ int4  g_flA[P_];                // (pixel, cand0, cand1, cand2)
__device__ int   g_flB[P_];

// ---- k_main smem layout (BM=128, BN=32, double-buffered B) ----------------
#define AW       132                    // words per row (132%32==4 -> conflict-free)
#define SBB      16896                  // one B buffer: 32 * 132 * 4
#define OFF_B    67584                  // SA: 128 x 132 words
#define OFF_EEH  101376                 // 1024 f32
#define OFF_U3   105472                 // float[2][128][3]
#define OFF_I3   108544                 // int[2][128][3]
#define SMEM_DYN 111616                 // ~109KB -> 2 CTAs/SM

#define TIE_T    6.5e-5f                // 3.1e-5 ref-jitter bound + 6.5 sigma

// ---------------------------------------------------------------------------
// codebook -> fp16 + exact ||e||^2 ; resets flag counters
__global__ void k_cbsplit(const float* __restrict__ cb) {
    if (blockIdx.x == 0 && threadIdx.x == 0) { g_nA = 0; g_nB = 0; }
    int gw   = (blockIdx.x * blockDim.x + threadIdx.x) >> 5;
    int lane = threadIdx.x & 31;
    if (gw >= NC_) return;
    const float* r = cb + (size_t)gw * C_;
    float acc = 0.f;
    #pragma unroll
    for (int k = lane; k < C_; k += 32) {
        float v = r[k];
        acc = fmaf(v, v, acc);
        g_ch[(size_t)gw * C_ + k] = __float2half_rn(v);
    }
    #pragma unroll
    for (int o = 16; o; o >>= 1) acc += __shfl_xor_sync(0xffffffffu, acc, o);
    if (!lane) g_ee[gw] = acc;
}

// ---------------------------------------------------------------------------
__device__ __forceinline__ void mma_f16(float* c, uint32_t a0, uint32_t a1,
                                        uint32_t a2, uint32_t a3,
                                        uint32_t b0, uint32_t b1) {
    asm volatile(
        "mma.sync.aligned.m16n8k16.row.col.f32.f16.f16.f32 "
        "{%0,%1,%2,%3}, {%4,%5,%6,%7}, {%8,%9}, {%0,%1,%2,%3};"
        : "+f"(c[0]), "+f"(c[1]), "+f"(c[2]), "+f"(c[3])
        : "r"(a0), "r"(a1), "r"(a2), "r"(a3), "r"(b0), "r"(b1));
}

// stable 3-slot sorted insert (strict <): ties keep earlier-processed entry
__device__ __forceinline__ void ins3(float* lu, int* li, float u, int n) {
    if (u < lu[0]) {
        lu[2] = lu[1]; li[2] = li[1];
        lu[1] = lu[0]; li[1] = li[0];
        lu[0] = u;     li[0] = n;
    } else if (u < lu[1]) {
        lu[2] = lu[1]; li[2] = li[1];
        lu[1] = u;     li[1] = n;
    } else if (u < lu[2]) {
        lu[2] = u;     li[2] = n;
    }
}

__device__ __forceinline__ uint32_t smem_u32(const void* p) {
    uint32_t a;
    asm("{ .reg .u64 t; cvta.to.shared.u64 t, %1; cvt.u32.u64 %0, t; }"
        : "=r"(a) : "l"(p));
    return a;
}

// stage one 32-code fp16 B tile (16KB) into smem buffer via cp.async
__device__ __forceinline__ void stage_tile(uint32_t sbB, int buf, int n0, int tid) {
    uint32_t bb = sbB + (buf ? SBB : 0);
    #pragma unroll
    for (int it = 0; it < 4; ++it) {
        int i = tid + it * 256;              // 0..1023 16B chunks
        int n = i >> 5;
        int q = i & 31;
        const __half* src = g_ch + (size_t)(n0 + n) * C_ + q * 8;
        uint32_t dst = bb + (uint32_t)(n * 528 + q * 16);
        asm volatile("cp.async.cg.shared.global [%0], [%1], 16;"
                     :: "r"(dst), "l"(src) : "memory");
    }
}

// ---------------------------------------------------------------------------
// main: 128 pixels x 1024 codes per CTA, fp16 HMMA with ldmatrix fragment
// feed (R10/R14 configuration: best measured, 193.7us).
// ---------------------------------------------------------------------------
__global__ __launch_bounds__(256, 2) void k_main(const float* __restrict__ z) {
    extern __shared__ __align__(16) char smem[];
    uint32_t* SA = (uint32_t*)smem;                       // [128][132] words
    float* s_eeh = (float*)(smem + OFF_EEH);
    float* SU    = (float*)(smem + OFF_U3);               // [2][128][3]
    int*   SI    = (int*)(smem + OFF_I3);

    const int tid  = threadIdx.x;
    const int lane = tid & 31;
    const int warp = tid >> 5;
    const int g    = lane >> 2;
    const int tc   = lane & 3;
    const int wm   = warp & 3;      // 4 x 32 M rows
    const int wn   = warp >> 2;     // 2 x 16 N cols
    const int m0   = blockIdx.x * 128;
    const uint32_t sbA = smem_u32(smem);
    const uint32_t sbB = smem_u32(smem + OFF_B);

    stage_tile(sbB, 0, 0, tid);
    asm volatile("cp.async.commit_group;" ::: "memory");

    for (int i = tid; i < NC_; i += 256)
        s_eeh[i] = __fmul_rn(0.5f, g_ee[i]);

    // ---- A: 128 pixels x 256 ch from NCHW z -> fp16, smem ----
    {
        int m   = tid & 127;
        int cp0 = tid >> 7;
        const float* zb = z + ((size_t)(m0 >> 10) * 256) * 1024 + (m0 & 1023) + m;
        uint32_t* arow = SA + (size_t)m * AW;
        #pragma unroll 4
        for (int cp = cp0; cp < 128; cp += 2) {
            float v0 = zb[(size_t)(2 * cp) << 10];
            float v1 = zb[(size_t)(2 * cp + 1) << 10];
            __half h0 = __float2half_rn(v0);
            __half h1 = __float2half_rn(v1);
            arow[cp] = (uint32_t)__half_as_ushort(h0) |
                       ((uint32_t)__half_as_ushort(h1) << 16);
        }
    }
    __syncthreads();

    float bu[4][3];
    int   bi[4][3];
    #pragma unroll
    for (int j = 0; j < 4; ++j) {
        bu[j][0] = bu[j][1] = bu[j][2] = 3.4e38f;
        bi[j][0] = bi[j][1] = bi[j][2] = 0;
    }

    // ldmatrix per-lane base addresses
    const uint32_t aA0 = sbA + (uint32_t)((wm * 32 + (lane & 15)) * AW) * 4
                             + (uint32_t)(lane >> 4) * 16;
    const uint32_t aA1 = aA0 + 16 * AW * 4;
    const uint32_t aBr = (uint32_t)((wn * 16 + ((lane >> 4) << 3) + (lane & 7))
                                    * AW) * 4
                       + (uint32_t)((lane >> 3) & 1) * 16;

    for (int nt = 0; nt < 32; ++nt) {
        asm volatile("cp.async.wait_group 0;" ::: "memory");
        __syncthreads();                       // tile nt visible; reuse safe

        if (nt < 31) {
            stage_tile(sbB, (nt + 1) & 1, (nt + 1) * 32, tid);
            asm volatile("cp.async.commit_group;" ::: "memory");
        }

        const uint32_t aB = sbB + (uint32_t)(nt & 1) * SBB + aBr;

        float acc[2][2][4];
        #pragma unroll
        for (int a = 0; a < 2; ++a)
            #pragma unroll
            for (int b = 0; b < 2; ++b)
                #pragma unroll
                for (int r = 0; r < 4; ++r) acc[a][b][r] = 0.f;

        #pragma unroll
        for (int kk = 0; kk < 16; ++kk) {
            uint32_t b00, b10, b01, b11;
            asm volatile(
                "ldmatrix.sync.aligned.m8n8.x4.shared.b16 {%0,%1,%2,%3}, [%4];"
                : "=r"(b00), "=r"(b10), "=r"(b01), "=r"(b11)
                : "r"(aB + kk * 32));
            uint32_t a0, a1, a2, a3;
            asm volatile(
                "ldmatrix.sync.aligned.m8n8.x4.shared.b16 {%0,%1,%2,%3}, [%4];"
                : "=r"(a0), "=r"(a1), "=r"(a2), "=r"(a3)
                : "r"(aA0 + kk * 32));
            mma_f16(acc[0][0], a0, a1, a2, a3, b00, b10);
            mma_f16(acc[0][1], a0, a1, a2, a3, b01, b11);
            asm volatile(
                "ldmatrix.sync.aligned.m8n8.x4.shared.b16 {%0,%1,%2,%3}, [%4];"
                : "=r"(a0), "=r"(a1), "=r"(a2), "=r"(a3)
                : "r"(aA1 + kk * 32));
            mma_f16(acc[1][0], a0, a1, a2, a3, b00, b10);
            mma_f16(acc[1][1], a0, a1, a2, a3, b01, b11);
        }

        // ---- epilogue: u = ee/2 - mm, top-3 insert (ascending n) ----
        #pragma unroll
        for (int mt = 0; mt < 2; ++mt)
            #pragma unroll
            for (int ntl = 0; ntl < 2; ++ntl)
                #pragma unroll
                for (int r = 0; r < 4; ++r) {
                    int lr = mt * 2 + (r >> 1);
                    int n  = nt * 32 + wn * 16 + ntl * 8 + tc * 2 + (r & 1);
                    float u = __fsub_rn(s_eeh[n], acc[mt][ntl][r]);
                    ins3(bu[lr], bi[lr], u, n);
                }
    }

    // ---- top-3 reduction: tc lanes via shfl, then two wn warps via smem ----
    #pragma unroll
    for (int j = 0; j < 4; ++j) {
        #pragma unroll
        for (int off = 1; off <= 2; off <<= 1) {
            float ou[3]; int oi[3];
            #pragma unroll
            for (int k = 0; k < 3; ++k) {
                ou[k] = __shfl_xor_sync(0xffffffffu, bu[j][k], off);
                oi[k] = __shfl_xor_sync(0xffffffffu, bi[j][k], off);
            }
            #pragma unroll
            for (int k = 0; k < 3; ++k) ins3(bu[j], bi[j], ou[k], oi[k]);
        }
        if (tc == 0) {
            int row = wm * 32 + (j >> 1) * 16 + (j & 1) * 8 + g;
            #pragma unroll
            for (int k = 0; k < 3; ++k) {
                SU[(wn * 128 + row) * 3 + k] = bu[j][k];
                SI[(wn * 128 + row) * 3 + k] = bi[j][k];
            }
        }
    }
    __syncthreads();

    if (tid < 128) {
        float lu[3]; int li[3];
        #pragma unroll
        for (int k = 0; k < 3; ++k) {
            lu[k] = SU[tid * 3 + k];
            li[k] = SI[tid * 3 + k];
        }
        #pragma unroll
        for (int k = 0; k < 3; ++k)
            ins3(lu, li, SU[(128 + tid) * 3 + k], SI[(128 + tid) * 3 + k]);

        int p = m0 + tid;
        g_idx[p] = li[0];
        float gap2 = __fsub_rn(lu[1], lu[0]);
        float gap3 = __fsub_rn(lu[2], lu[0]);
        if (gap3 < TIE_T) {
            int pos = atomicAdd(&g_nB, 1);
            g_flB[pos] = p;
        } else if (gap2 < TIE_T) {
            int pos = atomicAdd(&g_nA, 1);
            g_flA[pos] = make_int4(p, li[0], li[1], li[2]);
        }
    }
}

// ---------------------------------------------------------------------------
// rescue A: exact fp32 distances for <=3 candidate codes per flagged pixel.
// ---------------------------------------------------------------------------
__global__ __launch_bounds__(128) void k_rescueA(const float* __restrict__ z,
                                                 const float* __restrict__ cb) {
    int lane = threadIdx.x & 31;
    int warp = threadIdx.x >> 5;
    int total = g_nA;

    for (int it = blockIdx.x * 4 + warp; it < total; it += gridDim.x * 4) {
        int4 f = g_flA[it];
        int p = f.x;
        const float* zp = z + (size_t)(p >> 10) * (C_ * 1024) + (p & 1023);

        float zv[8];
        #pragma unroll
        for (int j = 0; j < 8; ++j)
            zv[j] = zp[(size_t)(lane + 32 * j) * 1024];

        float zz = 0.f;
        #pragma unroll
        for (int j = 0; j < 8; ++j) zz = fmaf(zv[j], zv[j], zz);
        #pragma unroll
        for (int o = 16; o; o >>= 1) zz += __shfl_xor_sync(0xffffffffu, zz, o);

        int cand[3] = { f.y, f.z, f.w };
        unsigned long long best = ~0ULL;
        #pragma unroll
        for (int c = 0; c < 3; ++c) {
            int n = cand[c];
            const float* cr = cb + (size_t)n * C_;
            float a = 0.f;
            #pragma unroll
            for (int jj = 0; jj < 8; ++jj)
                a = fmaf(cr[lane + 32 * jj], zv[jj], a);
            #pragma unroll
            for (int o = 16; o; o >>= 1)
                a += __shfl_xor_sync(0xffffffffu, a, o);
            float d = __fsub_rn(__fadd_rn(zz, g_ee[n]), __fmul_rn(2.0f, a));
            uint32_t bits = __float_as_uint(d);
            bits = (bits & 0x80000000u) ? ~bits : (bits | 0x80000000u);
            unsigned long long pk =
                ((unsigned long long)bits << 32) | (unsigned)n;
            if (pk < best) best = pk;
        }
        if (!lane) g_idx[p] = (int)(best & 0xFFFFFFFFu);
    }
}

// ---------------------------------------------------------------------------
// rescue B v3: one BLOCK per flagged pixel. z column in smem; thread t owns
// 4 codes, reading the K-major codebook SEQUENTIALLY per code (independent
// float4 streams -> high MLP, ~1KB loop body). Exact fp32 + first-index ties.
// ---------------------------------------------------------------------------
__global__ __launch_bounds__(256) void k_rescueB(const float* __restrict__ z,
                                                 const float* __restrict__ cb) {
    __shared__ float s_z[C_];
    __shared__ float s_zz;
    __shared__ unsigned long long s_best;

    int tid = threadIdx.x;
    int lane = tid & 31;

    for (int pos = blockIdx.x; pos < g_nB; pos += gridDim.x) {
        int p = g_flB[pos];
        s_z[tid] = z[(size_t)(p >> 10) * (C_ * 1024) +
                     (size_t)tid * 1024 + (p & 1023)];
        if (tid == 0) s_best = ~0ULL;
        __syncthreads();

        if (tid < 32) {
            float a = 0.f;
            #pragma unroll
            for (int j = 0; j < 8; ++j) {
                float v = s_z[tid + 32 * j];
                a = fmaf(v, v, a);
            }
            #pragma unroll
            for (int o = 16; o; o >>= 1) a += __shfl_xor_sync(0xffffffffu, a, o);
            if (!tid) s_zz = a;
        }
        __syncthreads();
        float zz = s_zz;

        // 4 codes per thread: sequential float4 streams over K
        float acc[4] = { 0.f, 0.f, 0.f, 0.f };
        const float* cr = cb + (size_t)(4 * tid) * C_;
        #pragma unroll 2
        for (int k = 0; k < C_; k += 4) {
            float4 zq = *(const float4*)&s_z[k];
            #pragma unroll
            for (int c = 0; c < 4; ++c) {
                float4 cq = *(const float4*)&cr[(size_t)c * C_ + k];
                acc[c] = fmaf(zq.x, cq.x, acc[c]);
                acc[c] = fmaf(zq.y, cq.y, acc[c]);
                acc[c] = fmaf(zq.z, cq.z, acc[c]);
                acc[c] = fmaf(zq.w, cq.w, acc[c]);
            }
        }

        unsigned long long lb = ~0ULL;
        #pragma unroll
        for (int c = 0; c < 4; ++c) {
            int n = 4 * tid + c;
            float d = __fsub_rn(__fadd_rn(zz, g_ee[n]),
                                __fmul_rn(2.0f, acc[c]));
            uint32_t bits = __float_as_uint(d);
            bits = (bits & 0x80000000u) ? ~bits : (bits | 0x80000000u);
            unsigned long long pk =
                ((unsigned long long)bits << 32) | (unsigned)n;
            if (pk < lb) lb = pk;
        }
        #pragma unroll
        for (int o = 16; o; o >>= 1) {
            unsigned long long ov = __shfl_xor_sync(0xffffffffu, lb, o);
            if (ov < lb) lb = ov;
        }
        if (!lane) atomicMin(&s_best, lb);
        __syncthreads();
        if (tid == 0) g_idx[p] = (int)(s_best & 0xFFFFFFFFu);
        __syncthreads();
    }
}

// ---------------------------------------------------------------------------
// outputs via smem transpose; straight_through = fl(fl(q - z) + z) exactly.
// ---------------------------------------------------------------------------
__global__ __launch_bounds__(256) void k_output(const float* __restrict__ cb,
                                                const float* __restrict__ zin,
                                                float* __restrict__ out,
                                                long long out_size) {
    __shared__ float tile[256][33];
    __shared__ int idxs[32];
    int bh = blockIdx.x;                     // b*32 + h
    int b = bh >> 5, h = bh & 31;
    int tid = threadIdx.x;

    if (tid < 32) idxs[tid] = g_idx[bh * 32 + tid];
    __syncthreads();

    #pragma unroll 8
    for (int w = 0; w < 32; ++w)
        tile[tid][w] = cb[(size_t)idxs[w] * C_ + tid];
    __syncthreads();

    long long obase = ((long long)b * 256) * 1024 + (long long)h * 32;
    int w = tid & 31;
    #pragma unroll 8
    for (int it = 0; it < 32; ++it) {
        int c = it * 8 + (tid >> 5);
        float q = tile[c][w];
        long long o = obase + (long long)c * 1024 + w;
        float zv = zin[o];
        float st = __fadd_rn(__fsub_rn(q, zv), zv);
        if (o < out_size) out[o] = q;
        if (NCHW_ + o < out_size) out[NCHW_ + o] = st;
    }
    if (tid < 32) {
        long long o = 2LL * NCHW_ + bh * 32 + tid;
        if (o < out_size) out[o] = (float)idxs[tid];
    }
}

// ---------------------------------------------------------------------------
extern "C" void kernel_launch(void* const* d_in, const int* in_sizes, int n_in,
                              void* d_out, int out_size) {
    const float* z  = (const float*)d_in[0];   // (64,256,32,32) f32
    const float* cb = (const float*)d_in[1];   // (1024,256) f32
    float* out = (float*)d_out;

    cudaFuncSetAttribute(k_main, cudaFuncAttributeMaxDynamicSharedMemorySize,
                         SMEM_DYN);

    // 4th launch (k_rescueB) lands in the ncu capture window
    k_cbsplit<<<NC_ / 8, 256>>>(cb);
    k_main<<<P_ / 128, 256, SMEM_DYN>>>(z);
    k_rescueA<<<1024, 128>>>(z, cb);
    k_rescueB<<<256, 256>>>(z, cb);
    k_output<<<2048, 256>>>(cb, z, out, (long long)out_size);
}